// round 1
// baseline (speedup 1.0000x reference)
#include <cuda_runtime.h>

#define H_HOPS   100000
#define NNODES   50000
#define MAX_PI   8
#define D        128
#define D_FF     512
#define TT       64
#define LN_EPS   1e-5f

#define RM        64
#define HS_STRIDE 513
#define XS_STRIDE 129
#define HS_FLOATS (RM * HS_STRIDE)          /* 32832 */
#define R2_FLOATS 24640                     /* max(xs 8256 + ws 16384, wg 16384 + tail) */
#define SMEM_FLOATS (HS_FLOATS + R2_FLOATS) /* 57472 */
#define SMEM_BYTES (SMEM_FLOATS * 4)        /* 229888 <= 232448 opt-in */

// ---- scratch (device globals: no allocation allowed) ----
__device__ float g_hop_hf[H_HOPS * D];   // pooled hop embeddings
__device__ float g_Wg[D_FF * TT];        // gamma[c] * W2[c][t]
__device__ float g_u[TT];                // sum_c gamma[c] W2[c][t]
__device__ float g_v[TT];                // sum_c beta[c]  W2[c][t] + b2[t]

// ---- packed f32x2 helpers (Blackwell FFMA2 path, PTX-only) ----
__device__ __forceinline__ unsigned long long pack2(float x) {
    unsigned long long r;
    asm("mov.b64 %0, {%1, %1};" : "=l"(r) : "f"(x));
    return r;
}
__device__ __forceinline__ void fma2(unsigned long long& d,
                                     unsigned long long a, unsigned long long b) {
    asm("fma.rn.f32x2 %0, %1, %2, %0;" : "+l"(d) : "l"(a), "l"(b));
}
__device__ __forceinline__ float2 unpack2(unsigned long long v) {
    float2 f;
    asm("mov.b64 {%0, %1}, %2;" : "=f"(f.x), "=f"(f.y) : "l"(v));
    return f;
}
__device__ __forceinline__ unsigned smem_u32(const void* p) {
    return (unsigned)__cvta_generic_to_shared(p);
}
__device__ __forceinline__ unsigned long long lds_b64(unsigned a) {
    unsigned long long v;
    asm("ld.shared.b64 %0, [%1];" : "=l"(v) : "r"(a));
    return v;
}

// ============================================================================
// Prep: fold LayerNorm affine into GEMM2 weights.
// ============================================================================
__global__ void prep_kernel(const float* __restrict__ gamma,
                            const float* __restrict__ beta,
                            const float* __restrict__ W2,
                            const float* __restrict__ b2) {
    int tid = threadIdx.x;
    for (int i = tid; i < D_FF * TT; i += 512)
        g_Wg[i] = gamma[i >> 6] * W2[i];
    if (tid < TT) {
        float u = 0.f, v = 0.f;
        for (int c = 0; c < D_FF; c++) {
            float w2 = W2[c * TT + tid];
            u += gamma[c] * w2;
            v += beta[c] * w2;
        }
        g_u[tid] = u;
        g_v[tid] = v + b2[tid];
    }
}

// ============================================================================
// Pooling: one warp per hop. Gather 9 tokens (L2-resident), masked softmax
// over scores = tok . w_q / sqrt(D), weighted sum -> g_hop_hf.
// ============================================================================
__global__ __launch_bounds__(256)
void pool_kernel(const float* __restrict__ hf,
                 const float* __restrict__ w_q,
                 const int* __restrict__ pi,
                 const int* __restrict__ stats,
                 const int* __restrict__ po) {
    int warp = threadIdx.x >> 5, lane = threadIdx.x & 31;
    int hop  = blockIdx.x * 8 + warp;
    int d0   = lane * 4;

    float4 wq = *reinterpret_cast<const float4*>(w_q + d0);

    float4 tok[MAX_PI + 1];
    float  sc[MAX_PI + 1];
    bool   ok[MAX_PI + 1];

    #pragma unroll
    for (int p = 0; p <= MAX_PI; p++) {
        int idx; bool v;
        if (p < MAX_PI) { idx = pi[hop * MAX_PI + p]; v = (stats[hop * MAX_PI + p] != -1); }
        else            { idx = po[hop];              v = true; }
        float4 t = *reinterpret_cast<const float4*>(hf + (long long)idx * D + d0);
        tok[p] = t; ok[p] = v;
        float s = t.x * wq.x + t.y * wq.y + t.z * wq.z + t.w * wq.w;
        #pragma unroll
        for (int o = 16; o; o >>= 1) s += __shfl_xor_sync(0xffffffffu, s, o);
        sc[p] = s * 0.08838834764831845f;   // 1/sqrt(128)
    }

    float m = -1e30f;
    #pragma unroll
    for (int p = 0; p <= MAX_PI; p++) if (ok[p] && sc[p] > m) m = sc[p];

    float denom = 0.f;
    float4 acc = make_float4(0.f, 0.f, 0.f, 0.f);
    #pragma unroll
    for (int p = 0; p <= MAX_PI; p++) {
        float e = ok[p] ? __expf(sc[p] - m) : 0.f;
        denom += e;
        acc.x += e * tok[p].x; acc.y += e * tok[p].y;
        acc.z += e * tok[p].z; acc.w += e * tok[p].w;
    }
    float inv = 1.f / denom;
    acc.x *= inv; acc.y *= inv; acc.z *= inv; acc.w *= inv;
    *reinterpret_cast<float4*>(g_hop_hf + (long long)hop * D + d0) = acc;
}

// ============================================================================
// Fused cls head: GEMM1(128->512) + bias + ReLU -> smem, LN stats,
// GEMM2(512->64) with folded LN affine -> logits.
// 64 rows per CTA, 256 threads. Lanes = rows (conflict-free odd strides),
// warps = column groups (W operands are warp-uniform b64 broadcasts).
// ============================================================================
__global__ __launch_bounds__(256, 1)
void head_kernel(const float* __restrict__ W1,
                 const float* __restrict__ b1,
                 float* __restrict__ out) {
    extern __shared__ float smem[];
    float* hs  = smem;                 // [64][513] relu(h) tile
    float* r2  = smem + HS_FLOATS;
    float* xs  = r2;                   // phase1: [64][129]
    float* wsf = r2 + RM * XS_STRIDE;  // phase1: [128][128] W1 chunk
    float* psum   = r2;                // phaseLN: [8][64]
    float* psumsq = r2 + 512;          // phaseLN: [8][64]
    float* wg  = r2;                   // phase2: [256][64] Wg chunk
    float* mu_s   = r2 + 24512;        // [64]
    float* rstd_s = r2 + 24576;        // [64]

    int tid = threadIdx.x;
    int w = tid >> 5, l = tid & 31;
    int row0 = blockIdx.x * RM;

    // ---- stage x tile (zero-pad tail rows) ----
    for (int i = tid; i < RM * D; i += 256) {
        int r = i >> 7, k = i & 127;
        int gr = row0 + r;
        xs[r * XS_STRIDE + k] = (gr < H_HOPS) ? g_hop_hf[(long long)gr * D + k] : 0.f;
    }

    float rs0 = 0.f, rq0 = 0.f, rs1 = 0.f, rq1 = 0.f;
    const float* xrow0 = xs + l * XS_STRIDE;
    const float* xrow1 = xs + (l + 32) * XS_STRIDE;
    unsigned ws_base = smem_u32(wsf);
    int cw = w * 16;   // this warp's 16 columns within the 128-col chunk

    // ---- GEMM1: 4 chunks of 128 columns ----
    for (int cc = 0; cc < 4; cc++) {
        int cbase = cc * 128;
        {   // stage W1[:, cbase:cbase+128] as float4
            const float4* W14 = reinterpret_cast<const float4*>(W1);
            float4* ws4 = reinterpret_cast<float4*>(wsf);
            for (int i = tid; i < 128 * 32; i += 256) {
                int k = i >> 5, cq = i & 31;
                ws4[k * 32 + cq] = W14[k * (D_FF / 4) + (cbase >> 2) + cq];
            }
        }
        __syncthreads();

        unsigned long long acc0[8], acc1[8];
        #pragma unroll
        for (int j = 0; j < 8; j++) { acc0[j] = 0ull; acc1[j] = 0ull; }

        #pragma unroll 4
        for (int k = 0; k < D; k++) {
            unsigned long long xa = pack2(xrow0[k]);
            unsigned long long xb = pack2(xrow1[k]);
            unsigned wa = ws_base + (unsigned)((k * 128 + cw) * 4);
            #pragma unroll
            for (int j = 0; j < 8; j++) {
                unsigned long long wv = lds_b64(wa + j * 8);
                fma2(acc0[j], xa, wv);
                fma2(acc1[j], xb, wv);
            }
        }

        // epilogue: bias + ReLU, store to hs, accumulate LN partials
        #pragma unroll
        for (int rr = 0; rr < 2; rr++) {
            int r = l + rr * 32;
            unsigned long long* acc = rr ? acc1 : acc0;
            float* hrow = hs + r * HS_STRIDE + cbase + cw;
            float s = 0.f, q = 0.f;
            #pragma unroll
            for (int j = 0; j < 8; j++) {
                float2 hv = unpack2(acc[j]);
                int c = cbase + cw + 2 * j;
                float h0 = fmaxf(hv.x + b1[c], 0.f);
                float h1 = fmaxf(hv.y + b1[c + 1], 0.f);
                hrow[2 * j]     = h0;
                hrow[2 * j + 1] = h1;
                s += h0 + h1;
                q += h0 * h0 + h1 * h1;
            }
            if (rr == 0) { rs0 += s; rq0 += q; } else { rs1 += s; rq1 += q; }
        }
        __syncthreads();
    }

    // ---- LN stats ----
    psum[w * 64 + l]        = rs0;  psum[w * 64 + l + 32]   = rs1;
    psumsq[w * 64 + l]      = rq0;  psumsq[w * 64 + l + 32] = rq1;
    __syncthreads();
    if (tid < 64) {
        float s = 0.f, q = 0.f;
        #pragma unroll
        for (int ww = 0; ww < 8; ww++) { s += psum[ww * 64 + tid]; q += psumsq[ww * 64 + tid]; }
        float mu  = s * (1.f / D_FF);
        float var = q * (1.f / D_FF) - mu * mu;
        mu_s[tid]   = mu;
        rstd_s[tid] = rsqrtf(var + LN_EPS);
    }
    __syncthreads();

    // ---- GEMM2: S = relu_h @ Wg, K=512 in 2 chunks of 256 ----
    unsigned long long a0[4], a1[4];
    #pragma unroll
    for (int j = 0; j < 4; j++) { a0[j] = 0ull; a1[j] = 0ull; }
    int tw = w * 8;
    unsigned wg_base = smem_u32(wg);
    const float* h0p = hs + l * HS_STRIDE;
    const float* h1p = hs + (l + 32) * HS_STRIDE;

    for (int ch = 0; ch < 2; ch++) {
        {
            float4* wg4 = reinterpret_cast<float4*>(wg);
            const float4* G4 = reinterpret_cast<const float4*>(g_Wg);
            for (int i = tid; i < 4096; i += 256) wg4[i] = G4[ch * 4096 + i];
        }
        __syncthreads();
        int kb = ch * 256;
        #pragma unroll 4
        for (int kk = 0; kk < 256; kk++) {
            unsigned long long ha = pack2(h0p[kb + kk]);
            unsigned long long hb = pack2(h1p[kb + kk]);
            unsigned wa = wg_base + (unsigned)((kk * TT + tw) * 4);
            #pragma unroll
            for (int j = 0; j < 4; j++) {
                unsigned long long wv = lds_b64(wa + j * 8);
                fma2(a0[j], ha, wv);
                fma2(a1[j], hb, wv);
            }
        }
        __syncthreads();
    }

    // ---- epilogue: logits = rstd*(S - mu*u) + v ----
    float4 u4a = *reinterpret_cast<const float4*>(g_u + tw);
    float4 u4b = *reinterpret_cast<const float4*>(g_u + tw + 4);
    float4 v4a = *reinterpret_cast<const float4*>(g_v + tw);
    float4 v4b = *reinterpret_cast<const float4*>(g_v + tw + 4);

    #pragma unroll
    for (int rr = 0; rr < 2; rr++) {
        int r = l + rr * 32;
        int grow = row0 + r;
        if (grow >= H_HOPS) continue;
        unsigned long long* acc = rr ? a1 : a0;
        float mu = mu_s[r], rstd = rstd_s[r];
        float2 s0 = unpack2(acc[0]), s1 = unpack2(acc[1]);
        float2 s2 = unpack2(acc[2]), s3 = unpack2(acc[3]);
        float4 o0, o1;
        o0.x = rstd * (s0.x - mu * u4a.x) + v4a.x;
        o0.y = rstd * (s0.y - mu * u4a.y) + v4a.y;
        o0.z = rstd * (s1.x - mu * u4a.z) + v4a.z;
        o0.w = rstd * (s1.y - mu * u4a.w) + v4a.w;
        o1.x = rstd * (s2.x - mu * u4b.x) + v4b.x;
        o1.y = rstd * (s2.y - mu * u4b.y) + v4b.y;
        o1.z = rstd * (s3.x - mu * u4b.z) + v4b.z;
        o1.w = rstd * (s3.y - mu * u4b.w) + v4b.w;
        float4* op = reinterpret_cast<float4*>(out + (long long)grow * TT + tw);
        op[0] = o0;
        op[1] = o1;
    }
}

// ============================================================================
extern "C" void kernel_launch(void* const* d_in, const int* in_sizes, int n_in,
                              void* d_out, int out_size) {
    const float* hf    = (const float*)d_in[0];
    const float* w_q   = (const float*)d_in[1];
    const float* W1    = (const float*)d_in[2];
    const float* b1    = (const float*)d_in[3];
    const float* gamma = (const float*)d_in[4];
    const float* beta  = (const float*)d_in[5];
    const float* W2    = (const float*)d_in[6];
    const float* b2    = (const float*)d_in[7];
    const int* pi      = (const int*)d_in[8];
    const int* stats   = (const int*)d_in[9];
    const int* po      = (const int*)d_in[10];
    float* out = (float*)d_out;

    cudaFuncSetAttribute(head_kernel,
                         cudaFuncAttributeMaxDynamicSharedMemorySize, SMEM_BYTES);

    prep_kernel<<<1, 512>>>(gamma, beta, W2, b2);
    pool_kernel<<<H_HOPS / 8, 256>>>(hf, w_q, pi, stats, po);
    head_kernel<<<(H_HOPS + RM - 1) / RM, 256, SMEM_BYTES>>>(W1, b1, out);
    (void)in_sizes; (void)n_in; (void)out_size;
}

// round 2
// speedup vs baseline: 1.0068x; 1.0068x over previous
#include <cuda_runtime.h>

#define H_HOPS   100000
#define NNODES   50000
#define MAX_PI   8
#define D        128
#define D_FF     512
#define TT       64
#define LN_EPS   1e-5f

#define RM        64
#define HS_STRIDE 513
#define XS_STRIDE 129
#define HS_FLOATS (RM * HS_STRIDE)          /* 32832 */
#define R2_FLOATS 24640                     /* max(xs 8256 + ws 16384, wg 16384 + tail) */
#define SMEM_FLOATS (HS_FLOATS + R2_FLOATS) /* 57472 */
#define SMEM_BYTES (SMEM_FLOATS * 4)        /* 229888 <= 232448 opt-in */

// ---- scratch (device globals: no allocation allowed) ----
__device__ float g_hop_hf[H_HOPS * D];   // pooled hop embeddings
__device__ float g_Wg[D_FF * TT];        // gamma[c] * W2[c][t]
__device__ float g_u[TT];                // sum_c gamma[c] W2[c][t]
__device__ float g_v[TT];                // sum_c beta[c]  W2[c][t] + b2[t]

// ---- packed f32x2 helpers (Blackwell FFMA2 path, PTX-only) ----
__device__ __forceinline__ unsigned long long pack2(float x) {
    unsigned long long r;
    asm("mov.b64 %0, {%1, %1};" : "=l"(r) : "f"(x));
    return r;
}
__device__ __forceinline__ void fma2(unsigned long long& d,
                                     unsigned long long a, unsigned long long b) {
    asm("fma.rn.f32x2 %0, %1, %2, %0;" : "+l"(d) : "l"(a), "l"(b));
}
__device__ __forceinline__ float2 unpack2(unsigned long long v) {
    float2 f;
    asm("mov.b64 {%0, %1}, %2;" : "=f"(f.x), "=f"(f.y) : "l"(v));
    return f;
}
__device__ __forceinline__ unsigned smem_u32(const void* p) {
    return (unsigned)__cvta_generic_to_shared(p);
}
__device__ __forceinline__ unsigned long long lds_b64(unsigned a) {
    unsigned long long v;
    asm("ld.shared.b64 %0, [%1];" : "=l"(v) : "r"(a));
    return v;
}

// ============================================================================
// Prep: fold LayerNorm affine into GEMM2 weights.
// ============================================================================
__global__ void prep_kernel(const float* __restrict__ gamma,
                            const float* __restrict__ beta,
                            const float* __restrict__ W2,
                            const float* __restrict__ b2) {
    int tid = threadIdx.x;
    for (int i = tid; i < D_FF * TT; i += 512)
        g_Wg[i] = gamma[i >> 6] * W2[i];
    if (tid < TT) {
        float u = 0.f, v = 0.f;
        for (int c = 0; c < D_FF; c++) {
            float w2 = W2[c * TT + tid];
            u += gamma[c] * w2;
            v += beta[c] * w2;
        }
        g_u[tid] = u;
        g_v[tid] = v + b2[tid];
    }
}

// ============================================================================
// Pooling: one warp per hop. Gather 9 tokens (L2-resident), masked softmax
// over scores = tok . w_q / sqrt(D), weighted sum -> g_hop_hf.
// ============================================================================
__global__ __launch_bounds__(256)
void pool_kernel(const float* __restrict__ hf,
                 const float* __restrict__ w_q,
                 const int* __restrict__ pi,
                 const int* __restrict__ stats,
                 const int* __restrict__ po) {
    int warp = threadIdx.x >> 5, lane = threadIdx.x & 31;
    int hop  = blockIdx.x * 8 + warp;
    int d0   = lane * 4;

    float4 wq = *reinterpret_cast<const float4*>(w_q + d0);

    float4 tok[MAX_PI + 1];
    float  sc[MAX_PI + 1];
    bool   ok[MAX_PI + 1];

    #pragma unroll
    for (int p = 0; p <= MAX_PI; p++) {
        int idx; bool v;
        if (p < MAX_PI) { idx = pi[hop * MAX_PI + p]; v = (stats[hop * MAX_PI + p] != -1); }
        else            { idx = po[hop];              v = true; }
        float4 t = *reinterpret_cast<const float4*>(hf + (long long)idx * D + d0);
        tok[p] = t; ok[p] = v;
        float s = t.x * wq.x + t.y * wq.y + t.z * wq.z + t.w * wq.w;
        #pragma unroll
        for (int o = 16; o; o >>= 1) s += __shfl_xor_sync(0xffffffffu, s, o);
        sc[p] = s * 0.08838834764831845f;   // 1/sqrt(128)
    }

    float m = -1e30f;
    #pragma unroll
    for (int p = 0; p <= MAX_PI; p++) if (ok[p] && sc[p] > m) m = sc[p];

    float denom = 0.f;
    float4 acc = make_float4(0.f, 0.f, 0.f, 0.f);
    #pragma unroll
    for (int p = 0; p <= MAX_PI; p++) {
        float e = ok[p] ? __expf(sc[p] - m) : 0.f;
        denom += e;
        acc.x += e * tok[p].x; acc.y += e * tok[p].y;
        acc.z += e * tok[p].z; acc.w += e * tok[p].w;
    }
    float inv = 1.f / denom;
    acc.x *= inv; acc.y *= inv; acc.z *= inv; acc.w *= inv;
    *reinterpret_cast<float4*>(g_hop_hf + (long long)hop * D + d0) = acc;
}

// ============================================================================
// Fused cls head: GEMM1(128->512) + bias + ReLU -> smem, LN stats,
// GEMM2(512->64) with folded LN affine -> logits.
// 64 rows per CTA, 256 threads. Lanes = rows (conflict-free odd strides),
// warps = column groups (W operands are warp-uniform b64 broadcasts).
// ============================================================================
__global__ __launch_bounds__(256, 1)
void head_kernel(const float* __restrict__ W1,
                 const float* __restrict__ b1,
                 float* __restrict__ out) {
    extern __shared__ float smem[];
    float* hs  = smem;                 // [64][513] relu(h) tile
    float* r2  = smem + HS_FLOATS;
    float* xs  = r2;                   // phase1: [64][129]
    float* wsf = r2 + RM * XS_STRIDE;  // phase1: [128][128] W1 chunk
    float* psum   = r2;                // phaseLN: [8][64]
    float* psumsq = r2 + 512;          // phaseLN: [8][64]
    float* wg  = r2;                   // phase2: [256][64] Wg chunk
    float* mu_s   = r2 + 24512;        // [64]
    float* rstd_s = r2 + 24576;        // [64]

    int tid = threadIdx.x;
    int w = tid >> 5, l = tid & 31;
    int row0 = blockIdx.x * RM;

    // ---- stage x tile (zero-pad tail rows) ----
    for (int i = tid; i < RM * D; i += 256) {
        int r = i >> 7, k = i & 127;
        int gr = row0 + r;
        xs[r * XS_STRIDE + k] = (gr < H_HOPS) ? g_hop_hf[(long long)gr * D + k] : 0.f;
    }

    float rs0 = 0.f, rq0 = 0.f, rs1 = 0.f, rq1 = 0.f;
    const float* xrow0 = xs + l * XS_STRIDE;
    const float* xrow1 = xs + (l + 32) * XS_STRIDE;
    unsigned ws_base = smem_u32(wsf);
    int cw = w * 16;   // this warp's 16 columns within the 128-col chunk

    // ---- GEMM1: 4 chunks of 128 columns ----
    for (int cc = 0; cc < 4; cc++) {
        int cbase = cc * 128;
        {   // stage W1[:, cbase:cbase+128] as float4
            const float4* W14 = reinterpret_cast<const float4*>(W1);
            float4* ws4 = reinterpret_cast<float4*>(wsf);
            for (int i = tid; i < 128 * 32; i += 256) {
                int k = i >> 5, cq = i & 31;
                ws4[k * 32 + cq] = W14[k * (D_FF / 4) + (cbase >> 2) + cq];
            }
        }
        __syncthreads();

        unsigned long long acc0[8], acc1[8];
        #pragma unroll
        for (int j = 0; j < 8; j++) { acc0[j] = 0ull; acc1[j] = 0ull; }

        #pragma unroll 4
        for (int k = 0; k < D; k++) {
            unsigned long long xa = pack2(xrow0[k]);
            unsigned long long xb = pack2(xrow1[k]);
            unsigned wa = ws_base + (unsigned)((k * 128 + cw) * 4);
            #pragma unroll
            for (int j = 0; j < 8; j++) {
                unsigned long long wv = lds_b64(wa + j * 8);
                fma2(acc0[j], xa, wv);
                fma2(acc1[j], xb, wv);
            }
        }

        // epilogue: bias + ReLU, store to hs, accumulate LN partials
        #pragma unroll
        for (int rr = 0; rr < 2; rr++) {
            int r = l + rr * 32;
            unsigned long long* acc = rr ? acc1 : acc0;
            float* hrow = hs + r * HS_STRIDE + cbase + cw;
            float s = 0.f, q = 0.f;
            #pragma unroll
            for (int j = 0; j < 8; j++) {
                float2 hv = unpack2(acc[j]);
                int c = cbase + cw + 2 * j;
                float h0 = fmaxf(hv.x + b1[c], 0.f);
                float h1 = fmaxf(hv.y + b1[c + 1], 0.f);
                hrow[2 * j]     = h0;
                hrow[2 * j + 1] = h1;
                s += h0 + h1;
                q += h0 * h0 + h1 * h1;
            }
            if (rr == 0) { rs0 += s; rq0 += q; } else { rs1 += s; rq1 += q; }
        }
        __syncthreads();
    }

    // ---- LN stats ----
    psum[w * 64 + l]        = rs0;  psum[w * 64 + l + 32]   = rs1;
    psumsq[w * 64 + l]      = rq0;  psumsq[w * 64 + l + 32] = rq1;
    __syncthreads();
    if (tid < 64) {
        float s = 0.f, q = 0.f;
        #pragma unroll
        for (int ww = 0; ww < 8; ww++) { s += psum[ww * 64 + tid]; q += psumsq[ww * 64 + tid]; }
        float mu  = s * (1.f / D_FF);
        float var = q * (1.f / D_FF) - mu * mu;
        mu_s[tid]   = mu;
        rstd_s[tid] = rsqrtf(var + LN_EPS);
    }
    __syncthreads();

    // ---- GEMM2: S = relu_h @ Wg, K=512 in 2 chunks of 256 ----
    unsigned long long a0[4], a1[4];
    #pragma unroll
    for (int j = 0; j < 4; j++) { a0[j] = 0ull; a1[j] = 0ull; }
    int tw = w * 8;
    unsigned wg_base = smem_u32(wg);
    const float* h0p = hs + l * HS_STRIDE;
    const float* h1p = hs + (l + 32) * HS_STRIDE;

    for (int ch = 0; ch < 2; ch++) {
        {
            float4* wg4 = reinterpret_cast<float4*>(wg);
            const float4* G4 = reinterpret_cast<const float4*>(g_Wg);
            for (int i = tid; i < 4096; i += 256) wg4[i] = G4[ch * 4096 + i];
        }
        __syncthreads();
        int kb = ch * 256;
        #pragma unroll 4
        for (int kk = 0; kk < 256; kk++) {
            unsigned long long ha = pack2(h0p[kb + kk]);
            unsigned long long hb = pack2(h1p[kb + kk]);
            unsigned wa = wg_base + (unsigned)((kk * TT + tw) * 4);
            #pragma unroll
            for (int j = 0; j < 4; j++) {
                unsigned long long wv = lds_b64(wa + j * 8);
                fma2(a0[j], ha, wv);
                fma2(a1[j], hb, wv);
            }
        }
        __syncthreads();
    }

    // ---- epilogue: logits = rstd*(S - mu*u) + v ----
    float4 u4a = *reinterpret_cast<const float4*>(g_u + tw);
    float4 u4b = *reinterpret_cast<const float4*>(g_u + tw + 4);
    float4 v4a = *reinterpret_cast<const float4*>(g_v + tw);
    float4 v4b = *reinterpret_cast<const float4*>(g_v + tw + 4);

    #pragma unroll
    for (int rr = 0; rr < 2; rr++) {
        int r = l + rr * 32;
        int grow = row0 + r;
        if (grow >= H_HOPS) continue;
        unsigned long long* acc = rr ? a1 : a0;
        float mu = mu_s[r], rstd = rstd_s[r];
        float2 s0 = unpack2(acc[0]), s1 = unpack2(acc[1]);
        float2 s2 = unpack2(acc[2]), s3 = unpack2(acc[3]);
        float4 o0, o1;
        o0.x = rstd * (s0.x - mu * u4a.x) + v4a.x;
        o0.y = rstd * (s0.y - mu * u4a.y) + v4a.y;
        o0.z = rstd * (s1.x - mu * u4a.z) + v4a.z;
        o0.w = rstd * (s1.y - mu * u4a.w) + v4a.w;
        o1.x = rstd * (s2.x - mu * u4b.x) + v4b.x;
        o1.y = rstd * (s2.y - mu * u4b.y) + v4b.y;
        o1.z = rstd * (s3.x - mu * u4b.z) + v4b.z;
        o1.w = rstd * (s3.y - mu * u4b.w) + v4b.w;
        float4* op = reinterpret_cast<float4*>(out + (long long)grow * TT + tw);
        op[0] = o0;
        op[1] = o1;
    }
}

// ============================================================================
extern "C" void kernel_launch(void* const* d_in, const int* in_sizes, int n_in,
                              void* d_out, int out_size) {
    const float* hf    = (const float*)d_in[0];
    const float* w_q   = (const float*)d_in[1];
    const float* W1    = (const float*)d_in[2];
    const float* b1    = (const float*)d_in[3];
    const float* gamma = (const float*)d_in[4];
    const float* beta  = (const float*)d_in[5];
    const float* W2    = (const float*)d_in[6];
    const float* b2    = (const float*)d_in[7];
    const int* pi      = (const int*)d_in[8];
    const int* stats   = (const int*)d_in[9];
    const int* po      = (const int*)d_in[10];
    float* out = (float*)d_out;

    cudaFuncSetAttribute(head_kernel,
                         cudaFuncAttributeMaxDynamicSharedMemorySize, SMEM_BYTES);

    prep_kernel<<<1, 512>>>(gamma, beta, W2, b2);
    pool_kernel<<<H_HOPS / 8, 256>>>(hf, w_q, pi, stats, po);
    head_kernel<<<(H_HOPS + RM - 1) / RM, 256, SMEM_BYTES>>>(W1, b1, out);
    (void)in_sizes; (void)n_in; (void)out_size;
}

// round 5
// speedup vs baseline: 2.5657x; 2.5483x over previous
#include <cuda_runtime.h>
#include <cuda_bf16.h>
#include <cstdint>

#define H_HOPS   100000
#define MAX_PI   8
#define D        128
#define D_FF     512
#define TT       64
#define LN_EPS   1e-5f
#define TILE_M   128
#define NCHUNK   8

// ---- smem map (bytes) ----
#define XS_HI   0u            /* 128 x 136 bf16 = 34816 */
#define XS_LO   34816u
#define BUF0    69632u        /* double-buffered weight stage */
#define BUFSZ   53248u        /* W1H 17408 | W1L 17408 | WGH 9216 | WGL 9216 */
#define W1L_OFF 17408u
#define WGH_OFF 34816u
#define WGL_OFF 44032u
#define B1S     176128u       /* 512 f32 */
#define USOFF   178176u       /* 64 f32 */
#define VSOFF   178432u
#define MUSOFF  178688u       /* 128 f32 */
#define RSTOFF  179200u
#define MB0     179712u
#define MB1     179720u
#define SMEM_SZ 179744u

// ---- device scratch ----
__device__ float g_hop[H_HOPS * D];
// W1^T split, chunk-major: [8][64 n][136 k] (k pad 128->136 for bank-free frags)
__device__ __align__(16) __nv_bfloat16 g_B1hi[NCHUNK * 64 * 136];
__device__ __align__(16) __nv_bfloat16 g_B1lo[NCHUNK * 64 * 136];
// (gamma*W2)^T split, chunk-major over k_ff: [8][64 n][72 k]
__device__ __align__(16) __nv_bfloat16 g_B2hi[NCHUNK * 64 * 72];
__device__ __align__(16) __nv_bfloat16 g_B2lo[NCHUNK * 64 * 72];
__device__ float g_u[TT];
__device__ float g_v[TT];

// ---- helpers ----
__device__ __forceinline__ unsigned smem_u32(const void* p) {
    return (unsigned)__cvta_generic_to_shared(p);
}
__device__ __forceinline__ uint32_t elect_one() {
    uint32_t p;
    asm volatile("{\n\t.reg .pred q;\n\telect.sync _|q, 0xFFFFFFFF;\n\t"
                 "selp.b32 %0, 1, 0, q;\n\t}" : "=r"(p));
    return p;
}
__device__ __forceinline__ unsigned cvt_bf16x2(float hi, float lo) {
    unsigned r;
    asm("cvt.rn.bf16x2.f32 %0, %1, %2;" : "=r"(r) : "f"(hi), "f"(lo));
    return r;
}
__device__ __forceinline__ float bf_lo(unsigned w) { return __uint_as_float(w << 16); }
__device__ __forceinline__ float bf_hi(unsigned w) { return __uint_as_float(w & 0xffff0000u); }
__device__ __forceinline__ void sts64(unsigned a, unsigned u0, unsigned u1) {
    asm volatile("st.shared.v2.b32 [%0], {%1, %2};" :: "r"(a), "r"(u0), "r"(u1) : "memory");
}
__device__ __forceinline__ unsigned lds32(unsigned a) {
    unsigned v;
    asm volatile("ld.shared.b32 %0, [%1];" : "=r"(v) : "r"(a));
    return v;
}
__device__ __forceinline__ void mma16816(float* d, const unsigned* a,
                                         unsigned b0, unsigned b1) {
    asm volatile(
        "mma.sync.aligned.m16n8k16.row.col.f32.bf16.bf16.f32 "
        "{%0,%1,%2,%3}, {%4,%5,%6,%7}, {%8,%9}, {%0,%1,%2,%3};"
        : "+f"(d[0]), "+f"(d[1]), "+f"(d[2]), "+f"(d[3])
        : "r"(a[0]), "r"(a[1]), "r"(a[2]), "r"(a[3]), "r"(b0), "r"(b1));
}

#define MBAR_INIT(a, c) \
    asm volatile("mbarrier.init.shared.b64 [%0], %1;" :: "r"(a), "r"(c) : "memory")
#define MBAR_EXPECT(a, b) \
    asm volatile("mbarrier.arrive.expect_tx.shared.b64 _, [%0], %1;" :: "r"(a), "r"(b) : "memory")
#define MBAR_WAIT(a, par) do {                                                  \
    asm volatile("{\n\t.reg .pred P1;\n\t"                                      \
        "WL_%=:\n\t"                                                            \
        "mbarrier.try_wait.parity.acquire.cta.shared::cta.b64 P1, [%0], %1, 0x989680;\n\t" \
        "@P1 bra.uni WD_%=;\n\tbra.uni WL_%=;\n\tWD_%=:\n\t}"                   \
        :: "r"(a), "r"(par) : "memory");                                        \
} while (0)
#define BULK_G2S(d, s, b, m) \
    asm volatile("cp.async.bulk.shared::cluster.global.mbarrier::complete_tx::bytes " \
                 "[%0], [%1], %2, [%3];" :: "r"(d), "l"(s), "r"(b), "r"(m) : "memory")

// ======================= prep: weight images + folded LN =======================
__global__ __launch_bounds__(256)
void prep_kernel(const float* __restrict__ W1, const float* __restrict__ gamma,
                 const float* __restrict__ beta, const float* __restrict__ W2,
                 const float* __restrict__ b2) {
    int g = blockIdx.x * 256 + threadIdx.x, gs = gridDim.x * 256;
    for (int i = g; i < D * D_FF; i += gs) {          // W1[k][n]
        int k = i >> 9, n = i & 511;
        float val = W1[i];
        __nv_bfloat16 h = __float2bfloat16(val);
        __nv_bfloat16 lo = __float2bfloat16(val - __bfloat162float(h));
        int idx = (n >> 6) * (64 * 136) + (n & 63) * 136 + k;
        g_B1hi[idx] = h; g_B1lo[idx] = lo;
    }
    for (int i = g; i < D_FF * TT; i += gs) {         // Wg[kf][n]
        int kf = i >> 6, n = i & 63;
        float val = gamma[kf] * W2[i];
        __nv_bfloat16 h = __float2bfloat16(val);
        __nv_bfloat16 lo = __float2bfloat16(val - __bfloat162float(h));
        int idx = (kf >> 6) * (64 * 72) + n * 72 + (kf & 63);
        g_B2hi[idx] = h; g_B2lo[idx] = lo;
    }
    if (blockIdx.x == 0) {
        __shared__ float pu[256], pv[256];
        int t = threadIdx.x & 63, part = threadIdx.x >> 6;
        float u = 0.f, v = 0.f;
        for (int c = part * 128; c < part * 128 + 128; c++) {
            float w2 = W2[c * TT + t];
            u += gamma[c] * w2; v += beta[c] * w2;
        }
        pu[threadIdx.x] = u; pv[threadIdx.x] = v;
        __syncthreads();
        if (threadIdx.x < 64) {
            float su = 0.f, sv = 0.f;
            for (int p = 0; p < 4; p++) { su += pu[p * 64 + t]; sv += pv[p * 64 + t]; }
            g_u[t] = su; g_v[t] = sv + b2[t];
        }
    }
}

// ======================= pool (unchanged, passing) =======================
__global__ __launch_bounds__(256)
void pool_kernel(const float* __restrict__ hf, const float* __restrict__ w_q,
                 const int* __restrict__ pi, const int* __restrict__ stats,
                 const int* __restrict__ po) {
    int warp = threadIdx.x >> 5, lane = threadIdx.x & 31;
    int hop = blockIdx.x * 8 + warp, d0 = lane * 4;
    float4 wq = *reinterpret_cast<const float4*>(w_q + d0);
    float4 tok[MAX_PI + 1]; float sc[MAX_PI + 1]; bool ok[MAX_PI + 1];
    #pragma unroll
    for (int p = 0; p <= MAX_PI; p++) {
        int idx; bool v;
        if (p < MAX_PI) { idx = pi[hop * MAX_PI + p]; v = (stats[hop * MAX_PI + p] != -1); }
        else            { idx = po[hop];              v = true; }
        float4 t = *reinterpret_cast<const float4*>(hf + (long long)idx * D + d0);
        tok[p] = t; ok[p] = v;
        float s = t.x * wq.x + t.y * wq.y + t.z * wq.z + t.w * wq.w;
        #pragma unroll
        for (int o = 16; o; o >>= 1) s += __shfl_xor_sync(0xffffffffu, s, o);
        sc[p] = s * 0.08838834764831845f;
    }
    float m = -1e30f;
    #pragma unroll
    for (int p = 0; p <= MAX_PI; p++) if (ok[p] && sc[p] > m) m = sc[p];
    float den = 0.f; float4 acc = make_float4(0.f, 0.f, 0.f, 0.f);
    #pragma unroll
    for (int p = 0; p <= MAX_PI; p++) {
        float e = ok[p] ? __expf(sc[p] - m) : 0.f;
        den += e;
        acc.x += e * tok[p].x; acc.y += e * tok[p].y;
        acc.z += e * tok[p].z; acc.w += e * tok[p].w;
    }
    float inv = 1.f / den;
    acc.x *= inv; acc.y *= inv; acc.z *= inv; acc.w *= inv;
    *reinterpret_cast<float4*>(g_hop + (long long)hop * D + d0) = acc;
}

// ======================= fused head: split-bf16 mma.sync =======================
__global__ __launch_bounds__(256)
void head_kernel(const float* __restrict__ b1, float* __restrict__ out) {
    extern __shared__ char smem[];
    const unsigned sb = smem_u32(smem);
    int tid = threadIdx.x, w = tid >> 5, lane = tid & 31;
    int grp = lane >> 2, q = lane & 3;
    int row0 = blockIdx.x * TILE_M, m0 = w * 16;

    if (tid == 0) { MBAR_INIT(sb + MB0, 1); MBAR_INIT(sb + MB1, 1); }
    __syncthreads();

    if (w == 0 && elect_one()) {          // prefetch chunks 0,1
        MBAR_EXPECT(sb + MB0, BUFSZ);
        BULK_G2S(sb + BUF0,           (const void*)(g_B1hi), 17408u, sb + MB0);
        BULK_G2S(sb + BUF0 + W1L_OFF, (const void*)(g_B1lo), 17408u, sb + MB0);
        BULK_G2S(sb + BUF0 + WGH_OFF, (const void*)(g_B2hi), 9216u,  sb + MB0);
        BULK_G2S(sb + BUF0 + WGL_OFF, (const void*)(g_B2lo), 9216u,  sb + MB0);
        MBAR_EXPECT(sb + MB1, BUFSZ);
        BULK_G2S(sb + BUF0 + BUFSZ,            (const void*)(g_B1hi + 8704), 17408u, sb + MB1);
        BULK_G2S(sb + BUF0 + BUFSZ + W1L_OFF,  (const void*)(g_B1lo + 8704), 17408u, sb + MB1);
        BULK_G2S(sb + BUF0 + BUFSZ + WGH_OFF,  (const void*)(g_B2hi + 4608), 9216u,  sb + MB1);
        BULK_G2S(sb + BUF0 + BUFSZ + WGL_OFF,  (const void*)(g_B2lo + 4608), 9216u,  sb + MB1);
    }

    float* b1s = (float*)(smem + B1S);
    for (int i = tid; i < D_FF; i += 256) b1s[i] = b1[i];
    if (tid < TT) {
        ((float*)(smem + USOFF))[tid] = g_u[tid];
        ((float*)(smem + VSOFF))[tid] = g_v[tid];
    }

    // stage x split (row stride 136 elems = 272B -> word stride 68 == 4 mod 32)
    for (int i = tid; i < TILE_M * 32; i += 256) {
        int r = i >> 5, c4 = (i & 31) << 2, gr = row0 + r;
        float4 x = make_float4(0.f, 0.f, 0.f, 0.f);
        if (gr < H_HOPS) x = *(const float4*)(g_hop + (size_t)gr * D + c4);
        unsigned h0 = cvt_bf16x2(x.y, x.x), h1 = cvt_bf16x2(x.w, x.z);
        unsigned a = sb + XS_HI + (unsigned)((r * 136 + c4) * 2);
        sts64(a, h0, h1);
        float e0 = x.x - bf_lo(h0), e1 = x.y - bf_hi(h0);
        float e2 = x.z - bf_lo(h1), e3 = x.w - bf_hi(h1);
        sts64(a + XS_LO, cvt_bf16x2(e1, e0), cvt_bf16x2(e3, e2));
    }
    __syncthreads();

    float acc2[32];
    #pragma unroll
    for (int i = 0; i < 32; i++) acc2[i] = 0.f;
    float s0 = 0.f, q0 = 0.f, s1 = 0.f, q1 = 0.f;
    const unsigned xbase = sb + XS_HI + (unsigned)((m0 + grp) * 272 + q * 4);

    for (int c = 0; c < NCHUNK; c++) {
        unsigned bb_ = sb + BUF0 + (unsigned)((c & 1) * BUFSZ);
        MBAR_WAIT(sb + MB0 + 8u * (unsigned)(c & 1), (unsigned)((c >> 1) & 1));

        float acc1[32];
        #pragma unroll
        for (int i = 0; i < 32; i++) acc1[i] = 0.f;
        unsigned wbase = bb_ + (unsigned)(grp * 272 + q * 4);

        #pragma unroll
        for (int s = 0; s < 8; s++) {
            unsigned xa = xbase + (unsigned)(s * 32);
            unsigned Ah[4] = { lds32(xa), lds32(xa + 2176), lds32(xa + 16), lds32(xa + 2192) };
            unsigned Al[4] = { lds32(xa + XS_LO), lds32(xa + XS_LO + 2176),
                               lds32(xa + XS_LO + 16), lds32(xa + XS_LO + 2192) };
            #pragma unroll
            for (int j = 0; j < 8; j++) {
                unsigned ba = wbase + (unsigned)(j * 2176 + s * 32);
                unsigned Bh0 = lds32(ba), Bh1 = lds32(ba + 16);
                unsigned Bl0 = lds32(ba + W1L_OFF), Bl1 = lds32(ba + W1L_OFF + 16);
                mma16816(acc1 + 4 * j, Ah, Bh0, Bh1);
                mma16816(acc1 + 4 * j, Ah, Bl0, Bl1);
                mma16816(acc1 + 4 * j, Al, Bh0, Bh1);
            }
        }

        // bias + relu + LN partials + register-local repack D-frag -> A-frag
        unsigned A2h[16], A2l[16];
        #pragma unroll
        for (int j = 0; j < 8; j++) {
            int col = c * 64 + 8 * j + 2 * q;
            float2 bb = *(const float2*)(smem + B1S + col * 4);
            float h0 = fmaxf(acc1[4 * j + 0] + bb.x, 0.f);
            float h1 = fmaxf(acc1[4 * j + 1] + bb.y, 0.f);
            float h2 = fmaxf(acc1[4 * j + 2] + bb.x, 0.f);
            float h3 = fmaxf(acc1[4 * j + 3] + bb.y, 0.f);
            s0 += h0 + h1; q0 = fmaf(h0, h0, fmaf(h1, h1, q0));
            s1 += h2 + h3; q1 = fmaf(h2, h2, fmaf(h3, h3, q1));
            unsigned p0 = cvt_bf16x2(h1, h0), p1 = cvt_bf16x2(h3, h2);
            int bi = (j >> 1) * 4 + (j & 1) * 2;
            A2h[bi] = p0; A2h[bi + 1] = p1;
            float e0 = h0 - bf_lo(p0), e1 = h1 - bf_hi(p0);
            float e2 = h2 - bf_lo(p1), e3 = h3 - bf_hi(p1);
            A2l[bi] = cvt_bf16x2(e1, e0); A2l[bi + 1] = cvt_bf16x2(e3, e2);
        }

        // GEMM2 partial over this 64-wide k slice
        unsigned gbase = bb_ + WGH_OFF + (unsigned)(grp * 144 + q * 4);
        #pragma unroll
        for (int t = 0; t < 4; t++) {
            #pragma unroll
            for (int j2 = 0; j2 < 8; j2++) {
                unsigned ba = gbase + (unsigned)(j2 * 1152 + t * 32);
                unsigned Bh0 = lds32(ba), Bh1 = lds32(ba + 16);
                unsigned Bl0 = lds32(ba + 9216), Bl1 = lds32(ba + 9216 + 16);
                mma16816(acc2 + 4 * j2, A2h + 4 * t, Bh0, Bh1);
                mma16816(acc2 + 4 * j2, A2h + 4 * t, Bl0, Bl1);
                mma16816(acc2 + 4 * j2, A2l + 4 * t, Bh0, Bh1);
            }
        }
        __syncthreads();
        if (c < NCHUNK - 2 && w == 0 && elect_one()) {
            int nc = c + 2;
            unsigned mb = sb + MB0 + 8u * (unsigned)(c & 1);
            MBAR_EXPECT(mb, BUFSZ);
            BULK_G2S(bb_,           (const void*)(g_B1hi + nc * 8704), 17408u, mb);
            BULK_G2S(bb_ + W1L_OFF, (const void*)(g_B1lo + nc * 8704), 17408u, mb);
            BULK_G2S(bb_ + WGH_OFF, (const void*)(g_B2hi + nc * 4608), 9216u,  mb);
            BULK_G2S(bb_ + WGL_OFF, (const void*)(g_B2lo + nc * 4608), 9216u,  mb);
        }
    }

    // LN stats: reduce over the 4 q-lanes sharing each row
    s0 += __shfl_xor_sync(0xffffffffu, s0, 1); s0 += __shfl_xor_sync(0xffffffffu, s0, 2);
    q0 += __shfl_xor_sync(0xffffffffu, q0, 1); q0 += __shfl_xor_sync(0xffffffffu, q0, 2);
    s1 += __shfl_xor_sync(0xffffffffu, s1, 1); s1 += __shfl_xor_sync(0xffffffffu, s1, 2);
    q1 += __shfl_xor_sync(0xffffffffu, q1, 1); q1 += __shfl_xor_sync(0xffffffffu, q1, 2);
    float* mus = (float*)(smem + MUSOFF);
    float* rst = (float*)(smem + RSTOFF);
    if (q == 0) {
        float mu = s0 * (1.f / D_FF), var = q0 * (1.f / D_FF) - mu * mu;
        mus[m0 + grp] = mu; rst[m0 + grp] = rsqrtf(var + LN_EPS);
        mu = s1 * (1.f / D_FF); var = q1 * (1.f / D_FF) - mu * mu;
        mus[m0 + grp + 8] = mu; rst[m0 + grp + 8] = rsqrtf(var + LN_EPS);
    }
    __syncwarp();
    float muA = mus[m0 + grp],     rsA = rst[m0 + grp];
    float muB = mus[m0 + grp + 8], rsB = rst[m0 + grp + 8];

    int ra = row0 + m0 + grp, rb = ra + 8;
    #pragma unroll
    for (int j2 = 0; j2 < 8; j2++) {
        int col = 8 * j2 + 2 * q;
        float2 uu = *(const float2*)(smem + USOFF + col * 4);
        float2 vv = *(const float2*)(smem + VSOFF + col * 4);
        if (ra < H_HOPS) {
            float2 o;
            o.x = rsA * (acc2[4 * j2 + 0] - muA * uu.x) + vv.x;
            o.y = rsA * (acc2[4 * j2 + 1] - muA * uu.y) + vv.y;
            *(float2*)(out + (size_t)ra * TT + col) = o;
        }
        if (rb < H_HOPS) {
            float2 o;
            o.x = rsB * (acc2[4 * j2 + 2] - muB * uu.x) + vv.x;
            o.y = rsB * (acc2[4 * j2 + 3] - muB * uu.y) + vv.y;
            *(float2*)(out + (size_t)rb * TT + col) = o;
        }
    }
}

extern "C" void kernel_launch(void* const* d_in, const int* in_sizes, int n_in,
                              void* d_out, int out_size) {
    const float* hf    = (const float*)d_in[0];
    const float* w_q   = (const float*)d_in[1];
    const float* W1    = (const float*)d_in[2];
    const float* b1    = (const float*)d_in[3];
    const float* gamma = (const float*)d_in[4];
    const float* beta  = (const float*)d_in[5];
    const float* W2    = (const float*)d_in[6];
    const float* b2    = (const float*)d_in[7];
    const int* pi      = (const int*)d_in[8];
    const int* stats   = (const int*)d_in[9];
    const int* po      = (const int*)d_in[10];
    float* out = (float*)d_out;

    cudaFuncSetAttribute(head_kernel,
                         cudaFuncAttributeMaxDynamicSharedMemorySize, SMEM_SZ);
    prep_kernel<<<64, 256>>>(W1, gamma, beta, W2, b2);
    pool_kernel<<<H_HOPS / 8, 256>>>(hf, w_q, pi, stats, po);
    head_kernel<<<(H_HOPS + TILE_M - 1) / TILE_M, 256, SMEM_SZ>>>(b1, out);
    (void)in_sizes; (void)n_in; (void)out_size;
}

// round 6
// speedup vs baseline: 2.6230x; 1.0223x over previous
#include <cuda_runtime.h>
#include <cuda_bf16.h>
#include <cstdint>

#define H_HOPS   100000
#define MAX_PI   8
#define D        128
#define D_FF     512
#define TT       64
#define LN_EPS   1e-5f
#define TILE_M   128
#define NCHUNK   8
#define POOL_BLOCKS (H_HOPS / 8)      /* 12500 */
#define PREP_BLOCKS 64

// ---- smem map (bytes) ----
#define XS_HI   0u            /* 128 x 136 bf16 = 34816 */
#define XS_LO   34816u
#define BUF0    69632u        /* double-buffered weight stage */
#define BUFSZ   53248u        /* W1H 17408 | W1L 17408 | WGH 9216 | WGL 9216 */
#define W1L_OFF 17408u
#define WGH_OFF 34816u
#define WGL_OFF 44032u
#define B1S     176128u       /* 512 f32 */
#define USOFF   178176u       /* 64 f32 */
#define VSOFF   178432u
#define MUSOFF  178688u       /* 128 f32 */
#define RSTOFF  179200u
#define MB0     179712u
#define MB1     179720u
#define SMEM_SZ 179744u

// ---- device scratch ----
__device__ float g_hop[H_HOPS * D];
__device__ __align__(16) __nv_bfloat16 g_B1hi[NCHUNK * 64 * 136];
__device__ __align__(16) __nv_bfloat16 g_B1lo[NCHUNK * 64 * 136];
__device__ __align__(16) __nv_bfloat16 g_B2hi[NCHUNK * 64 * 72];
__device__ __align__(16) __nv_bfloat16 g_B2lo[NCHUNK * 64 * 72];
__device__ float g_u[TT];
__device__ float g_v[TT];

// ---- helpers ----
__device__ __forceinline__ unsigned smem_u32(const void* p) {
    return (unsigned)__cvta_generic_to_shared(p);
}
__device__ __forceinline__ uint32_t elect_one() {
    uint32_t p;
    asm volatile("{\n\t.reg .pred q;\n\telect.sync _|q, 0xFFFFFFFF;\n\t"
                 "selp.b32 %0, 1, 0, q;\n\t}" : "=r"(p));
    return p;
}
__device__ __forceinline__ unsigned cvt_bf16x2(float hi, float lo) {
    unsigned r;
    asm("cvt.rn.bf16x2.f32 %0, %1, %2;" : "=r"(r) : "f"(hi), "f"(lo));
    return r;
}
__device__ __forceinline__ float bf_lo(unsigned w) { return __uint_as_float(w << 16); }
__device__ __forceinline__ float bf_hi(unsigned w) { return __uint_as_float(w & 0xffff0000u); }
__device__ __forceinline__ void sts64(unsigned a, unsigned u0, unsigned u1) {
    asm volatile("st.shared.v2.b32 [%0], {%1, %2};" :: "r"(a), "r"(u0), "r"(u1) : "memory");
}
__device__ __forceinline__ void ldsm_x4(unsigned* r, unsigned a) {
    asm volatile("ldmatrix.sync.aligned.m8n8.x4.shared.b16 {%0,%1,%2,%3}, [%4];"
                 : "=r"(r[0]), "=r"(r[1]), "=r"(r[2]), "=r"(r[3]) : "r"(a));
}
__device__ __forceinline__ void ldsm_x2(unsigned* r, unsigned a) {
    asm volatile("ldmatrix.sync.aligned.m8n8.x2.shared.b16 {%0,%1}, [%2];"
                 : "=r"(r[0]), "=r"(r[1]) : "r"(a));
}
__device__ __forceinline__ void mma16816(float* d, const unsigned* a,
                                         unsigned b0, unsigned b1) {
    asm volatile(
        "mma.sync.aligned.m16n8k16.row.col.f32.bf16.bf16.f32 "
        "{%0,%1,%2,%3}, {%4,%5,%6,%7}, {%8,%9}, {%0,%1,%2,%3};"
        : "+f"(d[0]), "+f"(d[1]), "+f"(d[2]), "+f"(d[3])
        : "r"(a[0]), "r"(a[1]), "r"(a[2]), "r"(a[3]), "r"(b0), "r"(b1));
}

#define MBAR_INIT(a, c) \
    asm volatile("mbarrier.init.shared.b64 [%0], %1;" :: "r"(a), "r"(c) : "memory")
#define MBAR_EXPECT(a, b) \
    asm volatile("mbarrier.arrive.expect_tx.shared.b64 _, [%0], %1;" :: "r"(a), "r"(b) : "memory")
#define MBAR_WAIT(a, par) do {                                                  \
    asm volatile("{\n\t.reg .pred P1;\n\t"                                      \
        "WL_%=:\n\t"                                                            \
        "mbarrier.try_wait.parity.acquire.cta.shared::cta.b64 P1, [%0], %1, 0x989680;\n\t" \
        "@P1 bra.uni WD_%=;\n\tbra.uni WL_%=;\n\tWD_%=:\n\t}"                   \
        :: "r"(a), "r"(par) : "memory");                                        \
} while (0)
#define BULK_G2S(d, s, b, m) \
    asm volatile("cp.async.bulk.shared::cluster.global.mbarrier::complete_tx::bytes " \
                 "[%0], [%1], %2, [%3];" :: "r"(d), "l"(s), "r"(b), "r"(m) : "memory")

// ============ fused pool + prep (independent work, one launch) ============
__global__ __launch_bounds__(256)
void pool_prep_kernel(const float* __restrict__ hf, const float* __restrict__ w_q,
                      const int* __restrict__ pi, const int* __restrict__ stats,
                      const int* __restrict__ po,
                      const float* __restrict__ W1, const float* __restrict__ gamma,
                      const float* __restrict__ beta, const float* __restrict__ W2,
                      const float* __restrict__ b2) {
    __shared__ float pu[256], pv[256];
    if (blockIdx.x >= POOL_BLOCKS) {
        // ---------------- prep branch ----------------
        int bid = blockIdx.x - POOL_BLOCKS;
        int g = bid * 256 + threadIdx.x, gs = PREP_BLOCKS * 256;
        for (int i = g; i < D * D_FF; i += gs) {          // W1[k][n]
            int k = i >> 9, n = i & 511;
            float val = W1[i];
            __nv_bfloat16 h = __float2bfloat16(val);
            __nv_bfloat16 lo = __float2bfloat16(val - __bfloat162float(h));
            int idx = (n >> 6) * (64 * 136) + (n & 63) * 136 + k;
            g_B1hi[idx] = h; g_B1lo[idx] = lo;
        }
        for (int i = g; i < D_FF * TT; i += gs) {         // Wg[kf][n]
            int kf = i >> 6, n = i & 63;
            float val = gamma[kf] * W2[i];
            __nv_bfloat16 h = __float2bfloat16(val);
            __nv_bfloat16 lo = __float2bfloat16(val - __bfloat162float(h));
            int idx = (kf >> 6) * (64 * 72) + n * 72 + (kf & 63);
            g_B2hi[idx] = h; g_B2lo[idx] = lo;
        }
        if (bid == 0) {
            int t = threadIdx.x & 63, part = threadIdx.x >> 6;
            float u = 0.f, v = 0.f;
            for (int c = part * 128; c < part * 128 + 128; c++) {
                float w2 = W2[c * TT + t];
                u += gamma[c] * w2; v += beta[c] * w2;
            }
            pu[threadIdx.x] = u; pv[threadIdx.x] = v;
            __syncthreads();
            if (threadIdx.x < 64) {
                float su = 0.f, sv = 0.f;
                for (int p = 0; p < 4; p++) { su += pu[p * 64 + t]; sv += pv[p * 64 + t]; }
                g_u[t] = su; g_v[t] = sv + b2[t];
            }
        }
        return;
    }
    // ---------------- pool branch ----------------
    int warp = threadIdx.x >> 5, lane = threadIdx.x & 31;
    int hop = blockIdx.x * 8 + warp, d0 = lane * 4;
    float4 wq = *reinterpret_cast<const float4*>(w_q + d0);
    float4 tok[MAX_PI + 1]; float sc[MAX_PI + 1]; bool ok[MAX_PI + 1];
    #pragma unroll
    for (int p = 0; p <= MAX_PI; p++) {
        int idx; bool v;
        if (p < MAX_PI) { idx = pi[hop * MAX_PI + p]; v = (stats[hop * MAX_PI + p] != -1); }
        else            { idx = po[hop];              v = true; }
        float4 t = *reinterpret_cast<const float4*>(hf + (long long)idx * D + d0);
        tok[p] = t; ok[p] = v;
        float s = t.x * wq.x + t.y * wq.y + t.z * wq.z + t.w * wq.w;
        #pragma unroll
        for (int o = 16; o; o >>= 1) s += __shfl_xor_sync(0xffffffffu, s, o);
        sc[p] = s * 0.08838834764831845f;
    }
    float m = -1e30f;
    #pragma unroll
    for (int p = 0; p <= MAX_PI; p++) if (ok[p] && sc[p] > m) m = sc[p];
    float den = 0.f; float4 acc = make_float4(0.f, 0.f, 0.f, 0.f);
    #pragma unroll
    for (int p = 0; p <= MAX_PI; p++) {
        float e = ok[p] ? __expf(sc[p] - m) : 0.f;
        den += e;
        acc.x += e * tok[p].x; acc.y += e * tok[p].y;
        acc.z += e * tok[p].z; acc.w += e * tok[p].w;
    }
    float inv = 1.f / den;
    acc.x *= inv; acc.y *= inv; acc.z *= inv; acc.w *= inv;
    *reinterpret_cast<float4*>(g_hop + (long long)hop * D + d0) = acc;
}

// ======================= fused head: split-bf16 mma.sync + ldmatrix =======================
__global__ __launch_bounds__(256)
void head_kernel(const float* __restrict__ b1, float* __restrict__ out) {
    extern __shared__ char smem[];
    const unsigned sb = smem_u32(smem);
    int tid = threadIdx.x, w = tid >> 5, lane = tid & 31;
    int grp = lane >> 2, q = lane & 3;
    int LL = lane & 15;
    int row0 = blockIdx.x * TILE_M, m0 = w * 16;

    if (tid == 0) { MBAR_INIT(sb + MB0, 1); MBAR_INIT(sb + MB1, 1); }
    __syncthreads();

    if (w == 0 && elect_one()) {          // prefetch chunks 0,1
        MBAR_EXPECT(sb + MB0, BUFSZ);
        BULK_G2S(sb + BUF0,           (const void*)(g_B1hi), 17408u, sb + MB0);
        BULK_G2S(sb + BUF0 + W1L_OFF, (const void*)(g_B1lo), 17408u, sb + MB0);
        BULK_G2S(sb + BUF0 + WGH_OFF, (const void*)(g_B2hi), 9216u,  sb + MB0);
        BULK_G2S(sb + BUF0 + WGL_OFF, (const void*)(g_B2lo), 9216u,  sb + MB0);
        MBAR_EXPECT(sb + MB1, BUFSZ);
        BULK_G2S(sb + BUF0 + BUFSZ,            (const void*)(g_B1hi + 8704), 17408u, sb + MB1);
        BULK_G2S(sb + BUF0 + BUFSZ + W1L_OFF,  (const void*)(g_B1lo + 8704), 17408u, sb + MB1);
        BULK_G2S(sb + BUF0 + BUFSZ + WGH_OFF,  (const void*)(g_B2hi + 4608), 9216u,  sb + MB1);
        BULK_G2S(sb + BUF0 + BUFSZ + WGL_OFF,  (const void*)(g_B2lo + 4608), 9216u,  sb + MB1);
    }

    float* b1s = (float*)(smem + B1S);
    for (int i = tid; i < D_FF; i += 256) b1s[i] = b1[i];
    if (tid < TT) {
        ((float*)(smem + USOFF))[tid] = g_u[tid];
        ((float*)(smem + VSOFF))[tid] = g_v[tid];
    }

    // stage x split (row stride 136 elems = 272B; word stride 68 == 4 mod 32)
    for (int i = tid; i < TILE_M * 32; i += 256) {
        int r = i >> 5, c4 = (i & 31) << 2, gr = row0 + r;
        float4 x = make_float4(0.f, 0.f, 0.f, 0.f);
        if (gr < H_HOPS) x = *(const float4*)(g_hop + (size_t)gr * D + c4);
        unsigned h0 = cvt_bf16x2(x.y, x.x), h1 = cvt_bf16x2(x.w, x.z);
        unsigned a = sb + XS_HI + (unsigned)((r * 136 + c4) * 2);
        sts64(a, h0, h1);
        float e0 = x.x - bf_lo(h0), e1 = x.y - bf_hi(h0);
        float e2 = x.z - bf_lo(h1), e3 = x.w - bf_hi(h1);
        sts64(a + XS_LO, cvt_bf16x2(e1, e0), cvt_bf16x2(e3, e2));
    }
    __syncthreads();

    float acc2[32];
    #pragma unroll
    for (int i = 0; i < 32; i++) acc2[i] = 0.f;
    float s0 = 0.f, q0 = 0.f, s1 = 0.f, q1 = 0.f;
    // ldmatrix lane-address bases
    const unsigned abase  = sb + XS_HI + (unsigned)((m0 + LL) * 272 + (lane >> 4) * 16);
    const unsigned bgeom1 = (unsigned)((LL & 7) * 272 + ((LL >> 3) & 1) * 16);
    const unsigned bgeom2 = (unsigned)((LL & 7) * 144 + ((LL >> 3) & 1) * 16);

    for (int c = 0; c < NCHUNK; c++) {
        unsigned bb_ = sb + BUF0 + (unsigned)((c & 1) * BUFSZ);
        MBAR_WAIT(sb + MB0 + 8u * (unsigned)(c & 1), (unsigned)((c >> 1) & 1));

        float acc1[32];
        #pragma unroll
        for (int i = 0; i < 32; i++) acc1[i] = 0.f;
        unsigned b1base = bb_ + bgeom1;

        #pragma unroll
        for (int s = 0; s < 8; s++) {
            unsigned Ah[4], Al[4];
            ldsm_x4(Ah, abase + (unsigned)(s * 32));
            ldsm_x4(Al, abase + XS_LO + (unsigned)(s * 32));
            #pragma unroll
            for (int j = 0; j < 8; j++) {
                unsigned Bh[2], Bl[2];
                unsigned ba = b1base + (unsigned)(j * 2176 + s * 32);
                ldsm_x2(Bh, ba);
                ldsm_x2(Bl, ba + W1L_OFF);
                mma16816(acc1 + 4 * j, Ah, Bh[0], Bh[1]);
                mma16816(acc1 + 4 * j, Ah, Bl[0], Bl[1]);
                mma16816(acc1 + 4 * j, Al, Bh[0], Bh[1]);
            }
        }

        // bias + relu + LN partials + register-local repack D-frag -> A-frag
        unsigned A2h[16], A2l[16];
        #pragma unroll
        for (int j = 0; j < 8; j++) {
            int col = c * 64 + 8 * j + 2 * q;
            float2 bb = *(const float2*)(smem + B1S + col * 4);
            float h0 = fmaxf(acc1[4 * j + 0] + bb.x, 0.f);
            float h1 = fmaxf(acc1[4 * j + 1] + bb.y, 0.f);
            float h2 = fmaxf(acc1[4 * j + 2] + bb.x, 0.f);
            float h3 = fmaxf(acc1[4 * j + 3] + bb.y, 0.f);
            s0 += h0 + h1; q0 = fmaf(h0, h0, fmaf(h1, h1, q0));
            s1 += h2 + h3; q1 = fmaf(h2, h2, fmaf(h3, h3, q1));
            unsigned p0 = cvt_bf16x2(h1, h0), p1 = cvt_bf16x2(h3, h2);
            int bi = (j >> 1) * 4 + (j & 1) * 2;
            A2h[bi] = p0; A2h[bi + 1] = p1;
            float e0 = h0 - bf_lo(p0), e1 = h1 - bf_hi(p0);
            float e2 = h2 - bf_lo(p1), e3 = h3 - bf_hi(p1);
            A2l[bi] = cvt_bf16x2(e1, e0); A2l[bi + 1] = cvt_bf16x2(e3, e2);
        }

        // GEMM2 partial over this 64-wide k slice
        unsigned g2base = bb_ + WGH_OFF + bgeom2;
        #pragma unroll
        for (int t = 0; t < 4; t++) {
            #pragma unroll
            for (int j2 = 0; j2 < 8; j2++) {
                unsigned Bh[2], Bl[2];
                unsigned ba = g2base + (unsigned)(j2 * 1152 + t * 32);
                ldsm_x2(Bh, ba);
                ldsm_x2(Bl, ba + 9216);
                mma16816(acc2 + 4 * j2, A2h + 4 * t, Bh[0], Bh[1]);
                mma16816(acc2 + 4 * j2, A2h + 4 * t, Bl[0], Bl[1]);
                mma16816(acc2 + 4 * j2, A2l + 4 * t, Bh[0], Bh[1]);
            }
        }
        __syncthreads();
        if (c < NCHUNK - 2 && w == 0 && elect_one()) {
            int nc = c + 2;
            unsigned mb = sb + MB0 + 8u * (unsigned)(c & 1);
            MBAR_EXPECT(mb, BUFSZ);
            BULK_G2S(bb_,           (const void*)(g_B1hi + nc * 8704), 17408u, mb);
            BULK_G2S(bb_ + W1L_OFF, (const void*)(g_B1lo + nc * 8704), 17408u, mb);
            BULK_G2S(bb_ + WGH_OFF, (const void*)(g_B2hi + nc * 4608), 9216u,  mb);
            BULK_G2S(bb_ + WGL_OFF, (const void*)(g_B2lo + nc * 4608), 9216u,  mb);
        }
    }

    // LN stats: reduce over the 4 q-lanes sharing each row
    s0 += __shfl_xor_sync(0xffffffffu, s0, 1); s0 += __shfl_xor_sync(0xffffffffu, s0, 2);
    q0 += __shfl_xor_sync(0xffffffffu, q0, 1); q0 += __shfl_xor_sync(0xffffffffu, q0, 2);
    s1 += __shfl_xor_sync(0xffffffffu, s1, 1); s1 += __shfl_xor_sync(0xffffffffu, s1, 2);
    q1 += __shfl_xor_sync(0xffffffffu, q1, 1); q1 += __shfl_xor_sync(0xffffffffu, q1, 2);
    float* mus = (float*)(smem + MUSOFF);
    float* rst = (float*)(smem + RSTOFF);
    if (q == 0) {
        float mu = s0 * (1.f / D_FF), var = q0 * (1.f / D_FF) - mu * mu;
        mus[m0 + grp] = mu; rst[m0 + grp] = rsqrtf(var + LN_EPS);
        mu = s1 * (1.f / D_FF); var = q1 * (1.f / D_FF) - mu * mu;
        mus[m0 + grp + 8] = mu; rst[m0 + grp + 8] = rsqrtf(var + LN_EPS);
    }
    __syncwarp();
    float muA = mus[m0 + grp],     rsA = rst[m0 + grp];
    float muB = mus[m0 + grp + 8], rsB = rst[m0 + grp + 8];

    int ra = row0 + m0 + grp, rb = ra + 8;
    #pragma unroll
    for (int j2 = 0; j2 < 8; j2++) {
        int col = 8 * j2 + 2 * q;
        float2 uu = *(const float2*)(smem + USOFF + col * 4);
        float2 vv = *(const float2*)(smem + VSOFF + col * 4);
        if (ra < H_HOPS) {
            float2 o;
            o.x = rsA * (acc2[4 * j2 + 0] - muA * uu.x) + vv.x;
            o.y = rsA * (acc2[4 * j2 + 1] - muA * uu.y) + vv.y;
            *(float2*)(out + (size_t)ra * TT + col) = o;
        }
        if (rb < H_HOPS) {
            float2 o;
            o.x = rsB * (acc2[4 * j2 + 2] - muB * uu.x) + vv.x;
            o.y = rsB * (acc2[4 * j2 + 3] - muB * uu.y) + vv.y;
            *(float2*)(out + (size_t)rb * TT + col) = o;
        }
    }
}

extern "C" void kernel_launch(void* const* d_in, const int* in_sizes, int n_in,
                              void* d_out, int out_size) {
    const float* hf    = (const float*)d_in[0];
    const float* w_q   = (const float*)d_in[1];
    const float* W1    = (const float*)d_in[2];
    const float* b1    = (const float*)d_in[3];
    const float* gamma = (const float*)d_in[4];
    const float* beta  = (const float*)d_in[5];
    const float* W2    = (const float*)d_in[6];
    const float* b2    = (const float*)d_in[7];
    const int* pi      = (const int*)d_in[8];
    const int* stats   = (const int*)d_in[9];
    const int* po      = (const int*)d_in[10];
    float* out = (float*)d_out;

    cudaFuncSetAttribute(head_kernel,
                         cudaFuncAttributeMaxDynamicSharedMemorySize, SMEM_SZ);
    pool_prep_kernel<<<POOL_BLOCKS + PREP_BLOCKS, 256>>>(hf, w_q, pi, stats, po,
                                                         W1, gamma, beta, W2, b2);
    head_kernel<<<(H_HOPS + TILE_M - 1) / TILE_M, 256, SMEM_SZ>>>(b1, out);
    (void)in_sizes; (void)n_in; (void)out_size;
}

// round 8
// speedup vs baseline: 2.7241x; 1.0385x over previous
#include <cuda_runtime.h>
#include <cuda_bf16.h>
#include <cstdint>

#define H_HOPS   100000
#define MAX_PI   8
#define D        128
#define D_FF     512
#define TT       64
#define LN_EPS   1e-5f
#define TILE_M   128
#define NCHUNK   8
#define POOL_BLOCKS (H_HOPS / 8)
#define PREP_BLOCKS 64

// ---- smem map (bytes) ----
#define XS_HI   0u            /* 128 x 136 bf16 = 34816 ; reused as f32 reduce buf */
#define XS_LO   34816u
#define BUF0    69632u
#define BUFSZ   53248u        /* W1H 17408 | W1L 17408 | WGH 9216 | WGL 9216 */
#define W1L_OFF 17408u
#define WGH_OFF 34816u
#define WGL_OFF 44032u
#define B1S     176128u       /* 512 f32 */
#define USOFF   178176u       /* 64 f32 */
#define VSOFF   178432u
#define SRED    178688u       /* 2 x 128 f32 */
#define QRED    179712u       /* 2 x 128 f32 */
#define MB0     180736u
#define MB1     180744u
#define SMEM_SZ 180768u

#define RSTRIDE 66            /* f32 stride of reduce buffer */

// ---- device scratch ----
__device__ float g_hop[H_HOPS * D];
__device__ __align__(16) __nv_bfloat16 g_B1hi[NCHUNK * 64 * 136];
__device__ __align__(16) __nv_bfloat16 g_B1lo[NCHUNK * 64 * 136];
__device__ __align__(16) __nv_bfloat16 g_B2hi[NCHUNK * 64 * 72];
__device__ __align__(16) __nv_bfloat16 g_B2lo[NCHUNK * 64 * 72];
__device__ float g_u[TT];
__device__ float g_v[TT];

// ---- helpers ----
__device__ __forceinline__ unsigned smem_u32(const void* p) {
    return (unsigned)__cvta_generic_to_shared(p);
}
__device__ __forceinline__ uint32_t elect_one() {
    uint32_t p;
    asm volatile("{\n\t.reg .pred q;\n\telect.sync _|q, 0xFFFFFFFF;\n\t"
                 "selp.b32 %0, 1, 0, q;\n\t}" : "=r"(p));
    return p;
}
__device__ __forceinline__ unsigned cvt_bf16x2(float hi, float lo) {
    unsigned r;
    asm("cvt.rn.bf16x2.f32 %0, %1, %2;" : "=r"(r) : "f"(hi), "f"(lo));
    return r;
}
__device__ __forceinline__ float bf_lo(unsigned w) { return __uint_as_float(w << 16); }
__device__ __forceinline__ float bf_hi(unsigned w) { return __uint_as_float(w & 0xffff0000u); }
__device__ __forceinline__ void sts64(unsigned a, unsigned u0, unsigned u1) {
    asm volatile("st.shared.v2.b32 [%0], {%1, %2};" :: "r"(a), "r"(u0), "r"(u1) : "memory");
}
__device__ __forceinline__ void ldsm_x4(unsigned* r, unsigned a) {
    asm volatile("ldmatrix.sync.aligned.m8n8.x4.shared.b16 {%0,%1,%2,%3}, [%4];"
                 : "=r"(r[0]), "=r"(r[1]), "=r"(r[2]), "=r"(r[3]) : "r"(a));
}
__device__ __forceinline__ void ldsm_x2(unsigned* r, unsigned a) {
    asm volatile("ldmatrix.sync.aligned.m8n8.x2.shared.b16 {%0,%1}, [%2];"
                 : "=r"(r[0]), "=r"(r[1]) : "r"(a));
}
__device__ __forceinline__ void mma16816(float* d, const unsigned* a,
                                         unsigned b0, unsigned b1) {
    asm volatile(
        "mma.sync.aligned.m16n8k16.row.col.f32.bf16.bf16.f32 "
        "{%0,%1,%2,%3}, {%4,%5,%6,%7}, {%8,%9}, {%0,%1,%2,%3};"
        : "+f"(d[0]), "+f"(d[1]), "+f"(d[2]), "+f"(d[3])
        : "r"(a[0]), "r"(a[1]), "r"(a[2]), "r"(a[3]), "r"(b0), "r"(b1));
}

#define MBAR_INIT(a, c) \
    asm volatile("mbarrier.init.shared.b64 [%0], %1;" :: "r"(a), "r"(c) : "memory")
#define MBAR_EXPECT(a, b) \
    asm volatile("mbarrier.arrive.expect_tx.shared.b64 _, [%0], %1;" :: "r"(a), "r"(b) : "memory")
#define MBAR_WAIT(a, par) do {                                                  \
    asm volatile("{\n\t.reg .pred P1;\n\t"                                      \
        "WL_%=:\n\t"                                                            \
        "mbarrier.try_wait.parity.acquire.cta.shared::cta.b64 P1, [%0], %1, 0x989680;\n\t" \
        "@P1 bra.uni WD_%=;\n\tbra.uni WL_%=;\n\tWD_%=:\n\t}"                   \
        :: "r"(a), "r"(par) : "memory");                                        \
} while (0)
#define BULK_G2S(d, s, b, m) \
    asm volatile("cp.async.bulk.shared::cluster.global.mbarrier::complete_tx::bytes " \
                 "[%0], [%1], %2, [%3];" :: "r"(d), "l"(s), "r"(b), "r"(m) : "memory")

// ============ fused pool + prep (independent work, one launch) ============
__global__ __launch_bounds__(256)
void pool_prep_kernel(const float* __restrict__ hf, const float* __restrict__ w_q,
                      const int* __restrict__ pi, const int* __restrict__ stats,
                      const int* __restrict__ po,
                      const float* __restrict__ W1, const float* __restrict__ gamma,
                      const float* __restrict__ beta, const float* __restrict__ W2,
                      const float* __restrict__ b2) {
    __shared__ float pu[256], pv[256];
    if (blockIdx.x >= POOL_BLOCKS) {
        int bid = blockIdx.x - POOL_BLOCKS;
        int g = bid * 256 + threadIdx.x, gs = PREP_BLOCKS * 256;
        for (int i = g; i < D * D_FF; i += gs) {
            int k = i >> 9, n = i & 511;
            float val = W1[i];
            __nv_bfloat16 h = __float2bfloat16(val);
            __nv_bfloat16 lo = __float2bfloat16(val - __bfloat162float(h));
            int idx = (n >> 6) * (64 * 136) + (n & 63) * 136 + k;
            g_B1hi[idx] = h; g_B1lo[idx] = lo;
        }
        for (int i = g; i < D_FF * TT; i += gs) {
            int kf = i >> 6, n = i & 63;
            float val = gamma[kf] * W2[i];
            __nv_bfloat16 h = __float2bfloat16(val);
            __nv_bfloat16 lo = __float2bfloat16(val - __bfloat162float(h));
            int idx = (kf >> 6) * (64 * 72) + n * 72 + (kf & 63);
            g_B2hi[idx] = h; g_B2lo[idx] = lo;
        }
        if (bid == 0) {
            int t = threadIdx.x & 63, part = threadIdx.x >> 6;
            float u = 0.f, v = 0.f;
            for (int c = part * 128; c < part * 128 + 128; c++) {
                float w2 = W2[c * TT + t];
                u += gamma[c] * w2; v += beta[c] * w2;
            }
            pu[threadIdx.x] = u; pv[threadIdx.x] = v;
            __syncthreads();
            if (threadIdx.x < 64) {
                float su = 0.f, sv = 0.f;
                for (int p = 0; p < 4; p++) { su += pu[p * 64 + t]; sv += pv[p * 64 + t]; }
                g_u[t] = su; g_v[t] = sv + b2[t];
            }
        }
        return;
    }
    int warp = threadIdx.x >> 5, lane = threadIdx.x & 31;
    int hop = blockIdx.x * 8 + warp, d0 = lane * 4;
    float4 wq = *reinterpret_cast<const float4*>(w_q + d0);
    float4 tok[MAX_PI + 1]; float sc[MAX_PI + 1]; bool ok[MAX_PI + 1];
    #pragma unroll
    for (int p = 0; p <= MAX_PI; p++) {
        int idx; bool v;
        if (p < MAX_PI) { idx = pi[hop * MAX_PI + p]; v = (stats[hop * MAX_PI + p] != -1); }
        else            { idx = po[hop];              v = true; }
        float4 t = *reinterpret_cast<const float4*>(hf + (long long)idx * D + d0);
        tok[p] = t; ok[p] = v;
        float s = t.x * wq.x + t.y * wq.y + t.z * wq.z + t.w * wq.w;
        #pragma unroll
        for (int o = 16; o; o >>= 1) s += __shfl_xor_sync(0xffffffffu, s, o);
        sc[p] = s * 0.08838834764831845f;
    }
    float m = -1e30f;
    #pragma unroll
    for (int p = 0; p <= MAX_PI; p++) if (ok[p] && sc[p] > m) m = sc[p];
    float den = 0.f; float4 acc = make_float4(0.f, 0.f, 0.f, 0.f);
    #pragma unroll
    for (int p = 0; p <= MAX_PI; p++) {
        float e = ok[p] ? __expf(sc[p] - m) : 0.f;
        den += e;
        acc.x += e * tok[p].x; acc.y += e * tok[p].y;
        acc.z += e * tok[p].z; acc.w += e * tok[p].w;
    }
    float inv = 1.f / den;
    acc.x *= inv; acc.y *= inv; acc.z *= inv; acc.w *= inv;
    *reinterpret_cast<float4*>(g_hop + (long long)hop * D + d0) = acc;
}

// ============== fused head: 16 warps, N-split, split-bf16 mma.sync ==============
__global__ __launch_bounds__(512, 1)
void head_kernel(const float* __restrict__ b1, float* __restrict__ out) {
    extern __shared__ char smem[];
    const unsigned sb = smem_u32(smem);
    int tid = threadIdx.x, w = tid >> 5, lane = tid & 31;
    int wm = w & 7, g2 = w >> 3;          // row-group / N-half
    int grp = lane >> 2, q = lane & 3;
    int LL = lane & 15;
    int row0 = blockIdx.x * TILE_M, m0 = wm * 16;

    if (tid == 0) { MBAR_INIT(sb + MB0, 1); MBAR_INIT(sb + MB1, 1); }
    __syncthreads();

    if (w == 0 && elect_one()) {          // prefetch chunks 0,1
        MBAR_EXPECT(sb + MB0, BUFSZ);
        BULK_G2S(sb + BUF0,           (const void*)(g_B1hi), 17408u, sb + MB0);
        BULK_G2S(sb + BUF0 + W1L_OFF, (const void*)(g_B1lo), 17408u, sb + MB0);
        BULK_G2S(sb + BUF0 + WGH_OFF, (const void*)(g_B2hi), 9216u,  sb + MB0);
        BULK_G2S(sb + BUF0 + WGL_OFF, (const void*)(g_B2lo), 9216u,  sb + MB0);
        MBAR_EXPECT(sb + MB1, BUFSZ);
        BULK_G2S(sb + BUF0 + BUFSZ,            (const void*)(g_B1hi + 8704), 17408u, sb + MB1);
        BULK_G2S(sb + BUF0 + BUFSZ + W1L_OFF,  (const void*)(g_B1lo + 8704), 17408u, sb + MB1);
        BULK_G2S(sb + BUF0 + BUFSZ + WGH_OFF,  (const void*)(g_B2hi + 4608), 9216u,  sb + MB1);
        BULK_G2S(sb + BUF0 + BUFSZ + WGL_OFF,  (const void*)(g_B2lo + 4608), 9216u,  sb + MB1);
    }

    float* b1s = (float*)(smem + B1S);
    for (int i = tid; i < D_FF; i += 512) b1s[i] = b1[i];
    if (tid < TT) {
        ((float*)(smem + USOFF))[tid] = g_u[tid];
        ((float*)(smem + VSOFF))[tid] = g_v[tid];
    }

    // stage x split (row stride 136 elems = 272B)
    for (int i = tid; i < TILE_M * 32; i += 512) {
        int r = i >> 5, c4 = (i & 31) << 2, gr = row0 + r;
        float4 x = make_float4(0.f, 0.f, 0.f, 0.f);
        if (gr < H_HOPS) x = *(const float4*)(g_hop + (size_t)gr * D + c4);
        unsigned h0 = cvt_bf16x2(x.y, x.x), h1 = cvt_bf16x2(x.w, x.z);
        unsigned a = sb + XS_HI + (unsigned)((r * 136 + c4) * 2);
        sts64(a, h0, h1);
        float e0 = x.x - bf_lo(h0), e1 = x.y - bf_hi(h0);
        float e2 = x.z - bf_lo(h1), e3 = x.w - bf_hi(h1);
        sts64(a + XS_LO, cvt_bf16x2(e1, e0), cvt_bf16x2(e3, e2));
    }
    __syncthreads();

    float acc2[32];
    #pragma unroll
    for (int i = 0; i < 32; i++) acc2[i] = 0.f;
    float s0 = 0.f, q0 = 0.f, s1 = 0.f, q1 = 0.f;
    const unsigned abase  = sb + XS_HI + (unsigned)((m0 + LL) * 272 + (lane >> 4) * 16);
    const unsigned bgeom1 = (unsigned)((LL & 7) * 272 + ((LL >> 3) & 1) * 16);
    const unsigned bgeom2 = (unsigned)((LL & 7) * 144 + ((LL >> 3) & 1) * 16);

    for (int c = 0; c < NCHUNK; c++) {
        unsigned bb_ = sb + BUF0 + (unsigned)((c & 1) * BUFSZ);
        MBAR_WAIT(sb + MB0 + 8u * (unsigned)(c & 1), (unsigned)((c >> 1) & 1));

        float acc1[16];
        #pragma unroll
        for (int i = 0; i < 16; i++) acc1[i] = 0.f;
        unsigned b1base = bb_ + bgeom1 + (unsigned)(g2 * 4 * 2176);

        #pragma unroll
        for (int s = 0; s < 8; s++) {
            unsigned Ah[4], Al[4];
            ldsm_x4(Ah, abase + (unsigned)(s * 32));
            ldsm_x4(Al, abase + XS_LO + (unsigned)(s * 32));
            #pragma unroll
            for (int j2 = 0; j2 < 4; j2++) {
                unsigned Bh[2], Bl[2];
                unsigned ba = b1base + (unsigned)(j2 * 2176 + s * 32);
                ldsm_x2(Bh, ba);
                ldsm_x2(Bl, ba + W1L_OFF);
                mma16816(acc1 + 4 * j2, Ah, Bh[0], Bh[1]);
                mma16816(acc1 + 4 * j2, Ah, Bl[0], Bl[1]);
                mma16816(acc1 + 4 * j2, Al, Bh[0], Bh[1]);
            }
        }

        // bias + relu + LN partials + register repack (our 32-col k-slice)
        unsigned A2h[8], A2l[8];
        #pragma unroll
        for (int j2 = 0; j2 < 4; j2++) {
            int col = c * 64 + g2 * 32 + 8 * j2 + 2 * q;
            float2 bb = *(const float2*)(smem + B1S + col * 4);
            float h0 = fmaxf(acc1[4 * j2 + 0] + bb.x, 0.f);
            float h1 = fmaxf(acc1[4 * j2 + 1] + bb.y, 0.f);
            float h2 = fmaxf(acc1[4 * j2 + 2] + bb.x, 0.f);
            float h3 = fmaxf(acc1[4 * j2 + 3] + bb.y, 0.f);
            s0 += h0 + h1; q0 = fmaf(h0, h0, fmaf(h1, h1, q0));
            s1 += h2 + h3; q1 = fmaf(h2, h2, fmaf(h3, h3, q1));
            unsigned p0 = cvt_bf16x2(h1, h0), p1 = cvt_bf16x2(h3, h2);
            int bi = (j2 >> 1) * 4 + (j2 & 1) * 2;
            A2h[bi] = p0; A2h[bi + 1] = p1;
            float e0 = h0 - bf_lo(p0), e1 = h1 - bf_hi(p0);
            float e2 = h2 - bf_lo(p1), e3 = h3 - bf_hi(p1);
            A2l[bi] = cvt_bf16x2(e1, e0); A2l[bi + 1] = cvt_bf16x2(e3, e2);
        }

        // GEMM2 partial over our 32-wide k slice
        unsigned g2base = bb_ + WGH_OFF + bgeom2;
        #pragma unroll
        for (int t = 0; t < 2; t++) {
            #pragma unroll
            for (int jn = 0; jn < 8; jn++) {
                unsigned Bh[2], Bl[2];
                unsigned ba = g2base + (unsigned)(jn * 1152 + (g2 * 2 + t) * 32);
                ldsm_x2(Bh, ba);
                ldsm_x2(Bl, ba + 9216);
                mma16816(acc2 + 4 * jn, A2h + 4 * t, Bh[0], Bh[1]);
                mma16816(acc2 + 4 * jn, A2h + 4 * t, Bl[0], Bl[1]);
                mma16816(acc2 + 4 * jn, A2l + 4 * t, Bh[0], Bh[1]);
            }
        }
        __syncthreads();
        if (c < NCHUNK - 2 && w == 0 && elect_one()) {
            int nc = c + 2;
            unsigned mb = sb + MB0 + 8u * (unsigned)(c & 1);
            MBAR_EXPECT(mb, BUFSZ);
            BULK_G2S(bb_,           (const void*)(g_B1hi + nc * 8704), 17408u, mb);
            BULK_G2S(bb_ + W1L_OFF, (const void*)(g_B1lo + nc * 8704), 17408u, mb);
            BULK_G2S(bb_ + WGH_OFF, (const void*)(g_B2hi + nc * 4608), 9216u,  mb);
            BULK_G2S(bb_ + WGL_OFF, (const void*)(g_B2lo + nc * 4608), 9216u,  mb);
        }
    }

    // LN partials: reduce over 4 q-lanes, publish per (half, row)
    s0 += __shfl_xor_sync(0xffffffffu, s0, 1); s0 += __shfl_xor_sync(0xffffffffu, s0, 2);
    q0 += __shfl_xor_sync(0xffffffffu, q0, 1); q0 += __shfl_xor_sync(0xffffffffu, q0, 2);
    s1 += __shfl_xor_sync(0xffffffffu, s1, 1); s1 += __shfl_xor_sync(0xffffffffu, s1, 2);
    q1 += __shfl_xor_sync(0xffffffffu, q1, 1); q1 += __shfl_xor_sync(0xffffffffu, q1, 2);
    float* sred = (float*)(smem + SRED);
    float* qred = (float*)(smem + QRED);
    if (q == 0) {
        sred[g2 * 128 + m0 + grp]     = s0;  qred[g2 * 128 + m0 + grp]     = q0;
        sred[g2 * 128 + m0 + grp + 8] = s1;  qred[g2 * 128 + m0 + grp + 8] = q1;
    }
    __syncthreads();                       // all XS reads done; partials visible

    // cross-half acc2 reduction through smem (reuse XS region)
    float* red = (float*)(smem + XS_HI);
    if (g2 == 1) {
        #pragma unroll
        for (int jn = 0; jn < 8; jn++) {
            int col = 8 * jn + 2 * q;
            *(float2*)(red + (m0 + grp) * RSTRIDE + col) =
                make_float2(acc2[4 * jn + 0], acc2[4 * jn + 1]);
            *(float2*)(red + (m0 + grp + 8) * RSTRIDE + col) =
                make_float2(acc2[4 * jn + 2], acc2[4 * jn + 3]);
        }
    }
    __syncthreads();
    if (g2 == 0) {
        float sA = sred[m0 + grp] + sred[128 + m0 + grp];
        float qA = qred[m0 + grp] + qred[128 + m0 + grp];
        float sB = sred[m0 + grp + 8] + sred[128 + m0 + grp + 8];
        float qB = qred[m0 + grp + 8] + qred[128 + m0 + grp + 8];
        float muA = sA * (1.f / D_FF), muB = sB * (1.f / D_FF);
        float rsA = rsqrtf(qA * (1.f / D_FF) - muA * muA + LN_EPS);
        float rsB = rsqrtf(qB * (1.f / D_FF) - muB * muB + LN_EPS);
        int ra = row0 + m0 + grp, rb = ra + 8;
        #pragma unroll
        for (int jn = 0; jn < 8; jn++) {
            int col = 8 * jn + 2 * q;
            float2 uu = *(const float2*)(smem + USOFF + col * 4);
            float2 vv = *(const float2*)(smem + VSOFF + col * 4);
            float2 pA = *(const float2*)(red + (m0 + grp) * RSTRIDE + col);
            float2 pB = *(const float2*)(red + (m0 + grp + 8) * RSTRIDE + col);
            if (ra < H_HOPS) {
                float2 o;
                o.x = rsA * (acc2[4 * jn + 0] + pA.x - muA * uu.x) + vv.x;
                o.y = rsA * (acc2[4 * jn + 1] + pA.y - muA * uu.y) + vv.y;
                *(float2*)(out + (size_t)ra * TT + col) = o;
            }
            if (rb < H_HOPS) {
                float2 o;
                o.x = rsB * (acc2[4 * jn + 2] + pB.x - muB * uu.x) + vv.x;
                o.y = rsB * (acc2[4 * jn + 3] + pB.y - muB * uu.y) + vv.y;
                *(float2*)(out + (size_t)rb * TT + col) = o;
            }
        }
    }
}

extern "C" void kernel_launch(void* const* d_in, const int* in_sizes, int n_in,
                              void* d_out, int out_size) {
    const float* hf    = (const float*)d_in[0];
    const float* w_q   = (const float*)d_in[1];
    const float* W1    = (const float*)d_in[2];
    const float* b1    = (const float*)d_in[3];
    const float* gamma = (const float*)d_in[4];
    const float* beta  = (const float*)d_in[5];
    const float* W2    = (const float*)d_in[6];
    const float* b2    = (const float*)d_in[7];
    const int* pi      = (const int*)d_in[8];
    const int* stats   = (const int*)d_in[9];
    const int* po      = (const int*)d_in[10];
    float* out = (float*)d_out;

    cudaFuncSetAttribute(head_kernel,
                         cudaFuncAttributeMaxDynamicSharedMemorySize, SMEM_SZ);
    pool_prep_kernel<<<POOL_BLOCKS + PREP_BLOCKS, 256>>>(hf, w_q, pi, stats, po,
                                                         W1, gamma, beta, W2, b2);
    head_kernel<<<(H_HOPS + TILE_M - 1) / TILE_M, 512, SMEM_SZ>>>(b1, out);
    (void)in_sizes; (void)n_in; (void)out_size;
}